// round 15
// baseline (speedup 1.0000x reference)
#include <cuda_runtime.h>
#include <cuda_fp16.h>
#include <cstdint>

#define THREADS 512
#define NWARP   16
#define EPS     0.10f

// dynamic smem layout (bytes)
#define OFF_ZS    0
#define OFF_AF    4096
#define OFF_WN    6144
#define OFF_RSP   10240
#define OFF_SMP   11264
#define OFF_RB    12288
#define OFF_ZN2   13440
#define OFF_INV   13504
#define OFF_QTHR  13568
#define OFF_BC    13632
#define OFF_QBUF  14336
#define QPITCH    68
#define SMEM_BYTES (14336 + 16 * 16 * QPITCH * 4)   // 83968

__device__ uint4  g_bfrag4[128 * 2 * 32];  // [ntg][kpair][lane] fp16 frags of -2e
__device__ float  g_wn1[1024];             // ||e_c||^2 + 1
__device__ double g_loss;
__device__ unsigned int g_done = 0;

__device__ __forceinline__ float rcpf(float x) {
    float r; asm("rcp.approx.f32 %0, %1;" : "=f"(r) : "f"(x)); return r;
}
__device__ __forceinline__ unsigned int ordered_u32(float f) {
    unsigned int u = __float_as_uint(f);
    return (u & 0x80000000u) ? ~u : (u | 0x80000000u);
}
__device__ __forceinline__ void mma_f16acc(uint32_t* c, const uint32_t* a,
                                           uint32_t b0, uint32_t b1) {
    asm volatile(
        "mma.sync.aligned.m16n8k16.row.col.f16.f16.f16.f16 "
        "{%0,%1}, {%2,%3,%4,%5}, {%6,%7}, {%0,%1};"
        : "+r"(c[0]), "+r"(c[1])
        : "r"(a[0]), "r"(a[1]), "r"(a[2]), "r"(a[3]), "r"(b0), "r"(b1));
}
__device__ __forceinline__ uint32_t h2pack(float a, float b) {
    __half2 h = __floats2half2_rn(a, b);
    return *(uint32_t*)&h;
}

// ---------------------------------------------------------------------------
__global__ void vq_prep(const float* __restrict__ cb) {
    __shared__ float rows[8 * 64];
    const int tid = threadIdx.x;
    const int ntg = blockIdx.x;
    if (ntg == 0 && tid == 0) g_loss = 0.0;
    ((float4*)rows)[tid] = ((const float4*)(cb + (size_t)ntg * 512))[tid];
    __syncthreads();
    if (tid < 8) {
        float s = 0.f;
        const float* r = rows + tid * 64;
#pragma unroll 16
        for (int k = 0; k < 64; k++) { float v = r[k]; s += v * v; }
        g_wn1[ntg * 8 + tid] = s + 1.f;
    }
    if (tid < 64) {
        const int lane = tid & 31;
        const int kp   = tid >> 5;
        const int g = lane >> 2, tq = lane & 3;
        const float* r = rows + g * 64;
        int ka = (2 * kp) * 16 + tq * 2;
        int kb = (2 * kp + 1) * 16 + tq * 2;
        uint4 v;
        v.x = h2pack(-2.f * r[ka],     -2.f * r[ka + 1]);
        v.y = h2pack(-2.f * r[ka + 8], -2.f * r[ka + 9]);
        v.z = h2pack(-2.f * r[kb],     -2.f * r[kb + 1]);
        v.w = h2pack(-2.f * r[kb + 8], -2.f * r[kb + 9]);
        g_bfrag4[(size_t)ntg * 64 + kp * 32 + lane] = v;
    }
}

// ---------------------------------------------------------------------------
// Main: 2 tiles of (16 rows x 1024 cols)/CTA; ring-prefetched GEMM;
// drain with inline per-warp exact refine. 16 warps, occ 2x512.
// ---------------------------------------------------------------------------
__global__ void __launch_bounds__(THREADS, 2)
vq_main(const float* __restrict__ z, const float* __restrict__ cb,
        float* __restrict__ q_out, float* __restrict__ zq_out,
        float* __restrict__ loss_out, int ncta) {
    extern __shared__ char sm[];
    float* z_s   = (float*)(sm + OFF_ZS);
    uint4* af_s  = (uint4*)(sm + OFF_AF);
    float* wn_s  = (float*)(sm + OFF_WN);
    float* rs_p  = (float*)(sm + OFF_RSP);
    float* sm_p  = (float*)(sm + OFF_SMP);
    unsigned long long* rowbest = (unsigned long long*)(sm + OFF_RB);
    float* zn2_s = (float*)(sm + OFF_ZN2);
    float* inv_s = (float*)(sm + OFF_INV);
    float* qthr_s= (float*)(sm + OFF_QTHR);
    int*   bc_s  = (int*)(sm + OFF_BC);
    float* qbuf  = (float*)(sm + OFF_QBUF);

    const int tid  = threadIdx.x;
    const int wid  = tid >> 5;
    const int lane = tid & 31;
    const int g    = lane >> 2;
    const int tq   = lane & 3;

    ((float2*)wn_s)[tid] = ((const float2*)g_wn1)[tid];

    float2 zpre = __ldg(((const float2*)(z + (size_t)blockIdx.x * 32 * 64)) + tid);
    float lp_total = 0.f;

#pragma unroll 1
    for (int tile = 0; tile < 2; tile++) {
        const int r0 = blockIdx.x * 32 + tile * 16;
        __syncthreads();
        ((float2*)z_s)[tid] = zpre;
        if (tile == 0)
            zpre = __ldg(((const float2*)(z + ((size_t)blockIdx.x * 32 + 16) * 64)) + tid);
        __syncthreads();

        if (tid < 128) {
            int kc = tid >> 5, ln = tid & 31;
            int gg = ln >> 2, qq = ln & 3;
            int k0 = kc * 16 + qq * 2;
            const float* zr0 = z_s + gg * 64;
            const float* zr1 = z_s + (gg + 8) * 64;
            uint4 v;
            v.x = h2pack(zr0[k0],     zr0[k0 + 1]);
            v.y = h2pack(zr1[k0],     zr1[k0 + 1]);
            v.z = h2pack(zr0[k0 + 8], zr0[k0 + 9]);
            v.w = h2pack(zr1[k0 + 8], zr1[k0 + 9]);
            af_s[tid] = v;
        }
        if (tid < 16) {
            float s = 0.f;
            const float* zr = z_s + tid * 64;
#pragma unroll 16
            for (int k = 0; k < 64; k++) { float v = zr[k]; s += v * v; }
            zn2_s[tid] = s;
            rowbest[tid] = 0ull;
        }
        __syncthreads();

        // ---- GEMM (f16 acc), B ring prefetch depth 2 ----
        uint32_t acc[8][2];
#pragma unroll
        for (int nt = 0; nt < 8; nt++) { acc[nt][0] = 0u; acc[nt][1] = 0u; }

        // frag (nt, kp) at bb + nt*64 + kp*32
        const uint4* bb = g_bfrag4 + (size_t)(wid * 8) * 64 + lane;
        uint4 brA = __ldg(bb);         // i=0 (nt0,kp0)
        uint4 brB = __ldg(bb + 64);    // i=1 (nt1,kp0)

#pragma unroll
        for (int kp = 0; kp < 2; kp++) {
            uint4 a0 = af_s[(kp * 2 + 0) * 32 + lane];
            uint4 a1 = af_s[(kp * 2 + 1) * 32 + lane];
            uint32_t ar0[4] = {a0.x, a0.y, a0.z, a0.w};
            uint32_t ar1[4] = {a1.x, a1.y, a1.z, a1.w};
#pragma unroll
            for (int nt = 0; nt < 8; nt++) {
                int i = kp * 8 + nt;
                uint4 b = (i & 1) ? brB : brA;
                int ip = i + 2;
                if (ip < 16) {
                    uint4 nb = __ldg(bb + (ip & 7) * 64 + (ip >> 3) * 32);
                    if (ip & 1) brB = nb; else brA = nb;
                }
                mma_f16acc(acc[nt], ar0, b.x, b.y);
                mma_f16acc(acc[nt], ar1, b.z, b.w);
            }
        }

        // ---- single epilogue pass: qun -> qbuf, rowsum, row-max S ----
        float rs[2]   = {0.f, 0.f};
        float smax[2] = {-3.4e38f, -3.4e38f};
        const int wc0 = wid * 64;
        const float zn0 = zn2_s[g];
        const float zn1 = zn2_s[g + 8];
        float* qbw = qbuf + wid * (16 * QPITCH);

#pragma unroll
        for (int nt = 0; nt < 8; nt++) {
            float2 dlo = __half22float2(*(const __half2*)&acc[nt][0]);
            float2 dhi = __half22float2(*(const __half2*)&acc[nt][1]);
            int c0 = wc0 + nt * 8 + tq * 2;
            float w0 = wn_s[c0], w1 = wn_s[c0 + 1];
            float S00 = dlo.x + zn0 + w0, S01 = dlo.y + zn0 + w1;
            float S10 = dhi.x + zn1 + w0, S11 = dhi.y + zn1 + w1;
            smax[0] = fmaxf(smax[0], fmaxf(S00, S01));
            smax[1] = fmaxf(smax[1], fmaxf(S10, S11));
            float q00 = rcpf(S00), q01 = rcpf(S01);
            float q10 = rcpf(S10), q11 = rcpf(S11);
            rs[0] += q00 + q01;
            rs[1] += q10 + q11;
            float2 v0 = {q00, q01}, v1 = {q10, q11};
            *(float2*)(qbw + g * QPITCH + nt * 8 + 2 * tq)       = v0;
            *(float2*)(qbw + (g + 8) * QPITCH + nt * 8 + 2 * tq) = v1;
        }
#pragma unroll
        for (int m = 1; m <= 2; m <<= 1) {
#pragma unroll
            for (int h = 0; h < 2; h++) {
                rs[h]   += __shfl_xor_sync(0xFFFFFFFFu, rs[h], m);
                smax[h]  = fmaxf(smax[h], __shfl_xor_sync(0xFFFFFFFFu, smax[h], m));
            }
        }
        if (tq == 0) {
#pragma unroll
            for (int h = 0; h < 2; h++) {
                rs_p[wid * 16 + g + h * 8] = rs[h];
                sm_p[wid * 16 + g + h * 8] = smax[h];
            }
        }
        __syncthreads();
        if (tid < 16) {
            float s = 0.f, sx = -3.4e38f;
#pragma unroll
            for (int w = 0; w < NWARP; w++) {
                s += rs_p[w * 16 + tid];
                sx = fmaxf(sx, sm_p[w * 16 + tid]);
            }
            inv_s[tid]  = 1.0f / s;
            qthr_s[tid] = 1.0f / (sx - EPS);   // candidate iff qun <= qthr
        }
        __syncthreads();

        // ---- drain: normalize + store + INLINE exact refine ----
#pragma unroll
        for (int it = 0; it < 8; it++) {
            int row  = (it >> 1) * 4 + (lane >> 3);
            int colf = (it & 1) * 32 + (lane & 7) * 4;
            float4 v = *(const float4*)(qbw + row * QPITCH + colf);
            float thr = qthr_s[row];
            unsigned m4 = (v.x <= thr ? 1u : 0u) | (v.y <= thr ? 2u : 0u) |
                          (v.z <= thr ? 4u : 0u) | (v.w <= thr ? 8u : 0u);
            float inv = inv_s[row];
            float4 o;
            o.x = v.x * inv; o.y = v.y * inv; o.z = v.z * inv; o.w = v.w * inv;
            *(float4*)(q_out + (size_t)(r0 + row) * 1024 + wc0 + colf) = o;

            unsigned bal = __ballot_sync(0xFFFFFFFFu, m4 != 0);
            while (bal) {
                int src = __ffs(bal) - 1;
                bal &= bal - 1;
                unsigned mm = __shfl_sync(0xFFFFFFFFu, m4, src);
                int rrow    = __shfl_sync(0xFFFFFFFFu, row, src);
                int cbase   = __shfl_sync(0xFFFFFFFFu, wc0 + colf, src);
                float2 zv = ((const float2*)(z_s + rrow * 64))[lane];
#pragma unroll 4
                for (int bit = 0; bit < 4; bit++) {
                    if (mm & (1u << bit)) {
                        int c = cbase + bit;
                        float2 ev = __ldg((const float2*)(cb + (size_t)c * 64) + lane);
                        float p = zv.x * ev.x + zv.y * ev.y;
#pragma unroll
                        for (int m = 16; m > 0; m >>= 1)
                            p += __shfl_xor_sync(0xFFFFFFFFu, p, m);
                        if (lane == 0) {
                            float d = zn2_s[rrow] + (wn_s[c] - 1.0f) - 2.f * p;
                            unsigned long long key =
                                ((unsigned long long)ordered_u32(d) << 32) |
                                (unsigned long long)(0xFFFFFFFFu - (unsigned int)c);
                            atomicMax(&rowbest[rrow], key);
                        }
                    }
                }
            }
        }
        __syncthreads();
        if (tid < 16)
            bc_s[tid] = (int)(0xFFFFFFFFu -
                              (unsigned int)(rowbest[tid] & 0xFFFFFFFFull));
        __syncthreads();

        // ---- gather z_q, store, loss partial ----
        if (tid < 256) {
            int rr = tid >> 4, j4 = tid & 15;
            int cbest = bc_s[rr];
            float4 e  = ((const float4*)(cb + (size_t)cbest * 64))[j4];
            float4 zv = ((const float4*)z_s)[rr * 16 + j4];
            ((float4*)(zq_out + (size_t)(r0 + rr) * 64))[j4] = e;
            float dx = e.x - zv.x, dy = e.y - zv.y,
                  dz = e.z - zv.z, dw = e.w - zv.w;
            lp_total += dx * dx + dy * dy + dz * dz + dw * dw;
        }
    }

    // ---- loss reduce + completion-counter finalize ----
#pragma unroll
    for (int m = 16; m > 0; m >>= 1)
        lp_total += __shfl_xor_sync(0xFFFFFFFFu, lp_total, m);
    if (lane == 0) rs_p[wid] = lp_total;
    __syncthreads();
    if (tid == 0) {
        float v = 0.f;
#pragma unroll
        for (int w = 0; w < NWARP; w++) v += rs_p[w];
        atomicAdd(&g_loss, (double)v);
        __threadfence();
        unsigned int old = atomicAdd(&g_done, 1u);
        if (old == (unsigned int)(ncta - 1)) {
            __threadfence();
            loss_out[0] = (float)(1.25 * g_loss / (65536.0 * 64.0));
            g_done = 0;
        }
    }
}

extern "C" void kernel_launch(void* const* d_in, const int* in_sizes, int n_in,
                              void* d_out, int out_size) {
    (void)in_sizes; (void)n_in; (void)out_size;
    const float* z  = (const float*)d_in[0];
    const float* cb = (const float*)d_in[1];
    float* out      = (float*)d_out;
    float* q_out    = out;
    float* zq_out   = out + (size_t)65536 * 1024;
    float* loss_out = zq_out + (size_t)65536 * 64;

    cudaFuncSetAttribute(vq_main, cudaFuncAttributeMaxDynamicSharedMemorySize,
                         SMEM_BYTES);
    vq_prep<<<128, 128>>>(cb);
    vq_main<<<2048, THREADS, SMEM_BYTES>>>(z, cb, q_out, zq_out, loss_out, 2048);
}

// round 16
// speedup vs baseline: 1.0995x; 1.0995x over previous
#include <cuda_runtime.h>
#include <cuda_fp16.h>
#include <cstdint>

#define THREADS 512
#define NWARP   16
#define EPS     0.10f
#define MAXCAND 256

// dynamic smem layout (bytes)
#define OFF_ZS    0
#define OFF_AF    4096
#define OFF_WN    6144
#define OFF_RSP   10240
#define OFF_SMP   11264
#define OFF_RB    12288
#define OFF_CAND  12416
#define OFF_ZN2   13440
#define OFF_INV   13504
#define OFF_QTHR  13568
#define OFF_NC    13696
#define OFF_QBUF  14336
#define QPITCH    68
#define SMEM_BYTES (14336 + 16 * 16 * QPITCH * 4)   // 83968

__device__ uint4  g_bfrag4[128 * 2 * 32];  // [ntg][kpair][lane] fp16 frags of -2e
__device__ float  g_wn1[1024];             // ||e_c||^2 + 1
__device__ double g_loss;
__device__ unsigned int g_done = 0;

__device__ __forceinline__ float rcpf(float x) {
    float r; asm("rcp.approx.f32 %0, %1;" : "=f"(r) : "f"(x)); return r;
}
__device__ __forceinline__ unsigned int ordered_u32(float f) {
    unsigned int u = __float_as_uint(f);
    return (u & 0x80000000u) ? ~u : (u | 0x80000000u);
}
__device__ __forceinline__ void mma_f16acc(uint32_t* c, const uint32_t* a,
                                           uint32_t b0, uint32_t b1) {
    asm volatile(
        "mma.sync.aligned.m16n8k16.row.col.f16.f16.f16.f16 "
        "{%0,%1}, {%2,%3,%4,%5}, {%6,%7}, {%0,%1};"
        : "+r"(c[0]), "+r"(c[1])
        : "r"(a[0]), "r"(a[1]), "r"(a[2]), "r"(a[3]), "r"(b0), "r"(b1));
}
__device__ __forceinline__ uint32_t h2pack(float a, float b) {
    __half2 h = __floats2half2_rn(a, b);
    return *(uint32_t*)&h;
}

// ---------------------------------------------------------------------------
__global__ void vq_prep(const float* __restrict__ cb) {
    __shared__ float rows[8 * 64];
    const int tid = threadIdx.x;
    const int ntg = blockIdx.x;
    if (ntg == 0 && tid == 0) g_loss = 0.0;
    ((float4*)rows)[tid] = ((const float4*)(cb + (size_t)ntg * 512))[tid];
    __syncthreads();
    if (tid < 8) {
        float s = 0.f;
        const float* r = rows + tid * 64;
#pragma unroll 16
        for (int k = 0; k < 64; k++) { float v = r[k]; s += v * v; }
        g_wn1[ntg * 8 + tid] = s + 1.f;
    }
    if (tid < 64) {
        const int lane = tid & 31;
        const int kp   = tid >> 5;
        const int g = lane >> 2, tq = lane & 3;
        const float* r = rows + g * 64;
        int ka = (2 * kp) * 16 + tq * 2;
        int kb = (2 * kp + 1) * 16 + tq * 2;
        uint4 v;
        v.x = h2pack(-2.f * r[ka],     -2.f * r[ka + 1]);
        v.y = h2pack(-2.f * r[ka + 8], -2.f * r[ka + 9]);
        v.z = h2pack(-2.f * r[kb],     -2.f * r[kb + 1]);
        v.w = h2pack(-2.f * r[kb + 8], -2.f * r[kb + 9]);
        g_bfrag4[(size_t)ntg * 64 + kp * 32 + lane] = v;
    }
}

// ---------------------------------------------------------------------------
// Main: 2 tiles of (16 rows x 1024 cols)/CTA; single-pass epilogue via qbuf
// (round-13 structure; bc_s phase removed — gather decodes rowbest directly)
// ---------------------------------------------------------------------------
__global__ void __launch_bounds__(THREADS, 2)
vq_main(const float* __restrict__ z, const float* __restrict__ cb,
        float* __restrict__ q_out, float* __restrict__ zq_out,
        float* __restrict__ loss_out, int ncta) {
    extern __shared__ char sm[];
    float* z_s   = (float*)(sm + OFF_ZS);
    uint4* af_s  = (uint4*)(sm + OFF_AF);
    float* wn_s  = (float*)(sm + OFF_WN);
    float* rs_p  = (float*)(sm + OFF_RSP);
    float* sm_p  = (float*)(sm + OFF_SMP);
    unsigned long long* rowbest = (unsigned long long*)(sm + OFF_RB);
    unsigned int* cand_s = (unsigned int*)(sm + OFF_CAND);
    float* zn2_s = (float*)(sm + OFF_ZN2);
    float* inv_s = (float*)(sm + OFF_INV);
    float* qthr_s= (float*)(sm + OFF_QTHR);
    int*   ncand_s = (int*)(sm + OFF_NC);
    float* qbuf  = (float*)(sm + OFF_QBUF);

    const int tid  = threadIdx.x;
    const int wid  = tid >> 5;
    const int lane = tid & 31;
    const int g    = lane >> 2;
    const int tq   = lane & 3;

    ((float2*)wn_s)[tid] = ((const float2*)g_wn1)[tid];

    float2 zpre = __ldg(((const float2*)(z + (size_t)blockIdx.x * 32 * 64)) + tid);
    float lp_total = 0.f;

#pragma unroll 1
    for (int tile = 0; tile < 2; tile++) {
        const int r0 = blockIdx.x * 32 + tile * 16;
        __syncthreads();
        ((float2*)z_s)[tid] = zpre;
        if (tile == 0)
            zpre = __ldg(((const float2*)(z + ((size_t)blockIdx.x * 32 + 16) * 64)) + tid);
        __syncthreads();

        if (tid < 128) {
            int kc = tid >> 5, ln = tid & 31;
            int gg = ln >> 2, qq = ln & 3;
            int k0 = kc * 16 + qq * 2;
            const float* zr0 = z_s + gg * 64;
            const float* zr1 = z_s + (gg + 8) * 64;
            uint4 v;
            v.x = h2pack(zr0[k0],     zr0[k0 + 1]);
            v.y = h2pack(zr1[k0],     zr1[k0 + 1]);
            v.z = h2pack(zr0[k0 + 8], zr0[k0 + 9]);
            v.w = h2pack(zr1[k0 + 8], zr1[k0 + 9]);
            af_s[tid] = v;
        }
        if (tid < 16) {
            float s = 0.f;
            const float* zr = z_s + tid * 64;
#pragma unroll 16
            for (int k = 0; k < 64; k++) { float v = zr[k]; s += v * v; }
            zn2_s[tid] = s;
            rowbest[tid] = 0ull;
        }
        if (tid == 0) *ncand_s = 0;
        __syncthreads();

        // ---- GEMM (f16 acc): warp owns cols wid*64..+63; 32 MMAs ----
        uint32_t acc[8][2];
#pragma unroll
        for (int nt = 0; nt < 8; nt++) { acc[nt][0] = 0u; acc[nt][1] = 0u; }

        const uint4* bb = g_bfrag4 + (size_t)(wid * 8) * 64 + lane;

#pragma unroll
        for (int kp = 0; kp < 2; kp++) {
            uint4 a0 = af_s[(kp * 2 + 0) * 32 + lane];
            uint4 a1 = af_s[(kp * 2 + 1) * 32 + lane];
            uint32_t ar0[4] = {a0.x, a0.y, a0.z, a0.w};
            uint32_t ar1[4] = {a1.x, a1.y, a1.z, a1.w};
#pragma unroll
            for (int nt = 0; nt < 8; nt++) {
                uint4 b = __ldg(bb + nt * 64 + kp * 32);
                mma_f16acc(acc[nt], ar0, b.x, b.y);
                mma_f16acc(acc[nt], ar1, b.z, b.w);
            }
        }

        // ---- single epilogue pass: qun -> qbuf, rowsum, row-max S ----
        float rs[2]   = {0.f, 0.f};
        float smax[2] = {-3.4e38f, -3.4e38f};
        const int wc0 = wid * 64;
        const float zn0 = zn2_s[g];
        const float zn1 = zn2_s[g + 8];
        float* qbw = qbuf + wid * (16 * QPITCH);

#pragma unroll
        for (int nt = 0; nt < 8; nt++) {
            float2 dlo = __half22float2(*(const __half2*)&acc[nt][0]);
            float2 dhi = __half22float2(*(const __half2*)&acc[nt][1]);
            int c0 = wc0 + nt * 8 + tq * 2;
            float w0 = wn_s[c0], w1 = wn_s[c0 + 1];
            float S00 = dlo.x + zn0 + w0, S01 = dlo.y + zn0 + w1;
            float S10 = dhi.x + zn1 + w0, S11 = dhi.y + zn1 + w1;
            smax[0] = fmaxf(smax[0], fmaxf(S00, S01));
            smax[1] = fmaxf(smax[1], fmaxf(S10, S11));
            float q00 = rcpf(S00), q01 = rcpf(S01);
            float q10 = rcpf(S10), q11 = rcpf(S11);
            rs[0] += q00 + q01;
            rs[1] += q10 + q11;
            float2 v0 = {q00, q01}, v1 = {q10, q11};
            *(float2*)(qbw + g * QPITCH + nt * 8 + 2 * tq)       = v0;
            *(float2*)(qbw + (g + 8) * QPITCH + nt * 8 + 2 * tq) = v1;
        }
#pragma unroll
        for (int m = 1; m <= 2; m <<= 1) {
#pragma unroll
            for (int h = 0; h < 2; h++) {
                rs[h]   += __shfl_xor_sync(0xFFFFFFFFu, rs[h], m);
                smax[h]  = fmaxf(smax[h], __shfl_xor_sync(0xFFFFFFFFu, smax[h], m));
            }
        }
        if (tq == 0) {
#pragma unroll
            for (int h = 0; h < 2; h++) {
                rs_p[wid * 16 + g + h * 8] = rs[h];
                sm_p[wid * 16 + g + h * 8] = smax[h];
            }
        }
        __syncthreads();
        if (tid < 16) {
            float s = 0.f, sx = -3.4e38f;
#pragma unroll
            for (int w = 0; w < NWARP; w++) {
                s += rs_p[w * 16 + tid];
                sx = fmaxf(sx, sm_p[w * 16 + tid]);
            }
            inv_s[tid]  = 1.0f / s;
            qthr_s[tid] = 1.0f / (sx - EPS);   // candidate iff qun <= qthr
        }
        __syncthreads();

        // ---- drain: normalize + candidate scan + coalesced STG.128 ----
#pragma unroll
        for (int it = 0; it < 8; it++) {
            int row  = (it >> 1) * 4 + (lane >> 3);
            int colf = (it & 1) * 32 + (lane & 7) * 4;
            float4 v = *(const float4*)(qbw + row * QPITCH + colf);
            float thr = qthr_s[row];
            bool c0 = v.x <= thr, c1 = v.y <= thr, c2 = v.z <= thr, c3 = v.w <= thr;
            unsigned bal = __ballot_sync(0xFFFFFFFFu, c0 | c1 | c2 | c3);
            if (bal) {
                int cc = wc0 + colf;
                if (c0) { int i = atomicAdd(ncand_s, 1);
                    if (i < MAXCAND) cand_s[i] = ((unsigned)row << 16) | (unsigned)cc; }
                if (c1) { int i = atomicAdd(ncand_s, 1);
                    if (i < MAXCAND) cand_s[i] = ((unsigned)row << 16) | (unsigned)(cc + 1); }
                if (c2) { int i = atomicAdd(ncand_s, 1);
                    if (i < MAXCAND) cand_s[i] = ((unsigned)row << 16) | (unsigned)(cc + 2); }
                if (c3) { int i = atomicAdd(ncand_s, 1);
                    if (i < MAXCAND) cand_s[i] = ((unsigned)row << 16) | (unsigned)(cc + 3); }
            }
            float inv = inv_s[row];
            v.x *= inv; v.y *= inv; v.z *= inv; v.w *= inv;
            *(float4*)(q_out + (size_t)(r0 + row) * 1024 + wc0 + colf) = v;
        }
        __syncthreads();

        // ---- exact fp32 refine (one warp per candidate) ----
        {
            int nc = *ncand_s < MAXCAND ? *ncand_s : MAXCAND;
            for (int i = wid; i < nc; i += NWARP) {
                unsigned int pc = cand_s[i];
                int rr = pc >> 16, c = pc & 0xFFFF;
                float2 zv = ((const float2*)(z_s + rr * 64))[lane];
                float2 ev = __ldg((const float2*)(cb + (size_t)c * 64) + lane);
                float p = zv.x * ev.x + zv.y * ev.y;
#pragma unroll
                for (int m = 16; m > 0; m >>= 1)
                    p += __shfl_xor_sync(0xFFFFFFFFu, p, m);
                if (lane == 0) {
                    float d = zn2_s[rr] + (wn_s[c] - 1.0f) - 2.f * p;
                    unsigned long long key =
                        ((unsigned long long)ordered_u32(d) << 32) |
                        (unsigned long long)(0xFFFFFFFFu - (unsigned int)c);
                    atomicMax(&rowbest[rr], key);
                }
            }
        }
        __syncthreads();

        // ---- gather z_q (decode rowbest inline), store, loss partial ----
        if (tid < 256) {
            int rr = tid >> 4, j4 = tid & 15;
            int cbest = (int)(0xFFFFFFFFu -
                              (unsigned int)(rowbest[rr] & 0xFFFFFFFFull));
            float4 e  = ((const float4*)(cb + (size_t)cbest * 64))[j4];
            float4 zv = ((const float4*)z_s)[rr * 16 + j4];
            ((float4*)(zq_out + (size_t)(r0 + rr) * 64))[j4] = e;
            float dx = e.x - zv.x, dy = e.y - zv.y,
                  dz = e.z - zv.z, dw = e.w - zv.w;
            lp_total += dx * dx + dy * dy + dz * dz + dw * dw;
        }
    }

    // ---- loss reduce + completion-counter finalize ----
#pragma unroll
    for (int m = 16; m > 0; m >>= 1)
        lp_total += __shfl_xor_sync(0xFFFFFFFFu, lp_total, m);
    if (lane == 0) rs_p[wid] = lp_total;
    __syncthreads();
    if (tid == 0) {
        float v = 0.f;
#pragma unroll
        for (int w = 0; w < NWARP; w++) v += rs_p[w];
        atomicAdd(&g_loss, (double)v);
        __threadfence();
        unsigned int old = atomicAdd(&g_done, 1u);
        if (old == (unsigned int)(ncta - 1)) {
            __threadfence();
            loss_out[0] = (float)(1.25 * g_loss / (65536.0 * 64.0));
            g_done = 0;
        }
    }
}

extern "C" void kernel_launch(void* const* d_in, const int* in_sizes, int n_in,
                              void* d_out, int out_size) {
    (void)in_sizes; (void)n_in; (void)out_size;
    const float* z  = (const float*)d_in[0];
    const float* cb = (const float*)d_in[1];
    float* out      = (float*)d_out;
    float* q_out    = out;
    float* zq_out   = out + (size_t)65536 * 1024;
    float* loss_out = zq_out + (size_t)65536 * 64;

    cudaFuncSetAttribute(vq_main, cudaFuncAttributeMaxDynamicSharedMemorySize,
                         SMEM_BYTES);
    vq_prep<<<128, 128>>>(cb);
    vq_main<<<2048, THREADS, SMEM_BYTES>>>(z, cb, q_out, zq_out, loss_out, 2048);
}